// round 16
// baseline (speedup 1.0000x reference)
#include <cuda_runtime.h>
#include <math.h>

// Problem constants (fixed by setup_inputs)
#define BS    16
#define T     1024
#define DF    80
#define DF4   20
#define SIZE  4096
#define TPB   128        // narrow kernel: quad per row -> 32 rows per block
#define RPB   32
#define GPB   4          // 8-row groups per narrow block
#define NZ    16         // split factor for WIDE groups
#define THRESH 96
#define GRPS  (SIZE / 8) // 512
#define TPAD  8
#define PT    (T + TPAD)
#define NROW  (BS * SIZE)
#define KMAX  150        // narrow h-tile rows in smem (150*320B = 48000B)
#define WGRID 256        // wide kernel blocks (x4 warps = 1024 work slots)
#define CGRID 64         // combine kernel blocks
#define FULLM 0xFFFFFFFFu

// Device scratch (allocation-free)
__device__ float g_cs[BS * PT];            // sorted centers (+INF pad)
__device__ __align__(16) float g_hp[BS * PT * DF];   // permuted h (0 pad)
__device__ int2  g_win[BS * GRPS];         // per 8-row group: union {wlo,whi}
__device__ float g_smax[NROW];             // per row: exact max score
__device__ __align__(16) float g_part[(size_t)NZ * NROW * DF];
__device__ float g_lpart[NZ * NROW];
__device__ int   g_qb[BS][GRPS];           // per-batch queues of WIDE groups
__device__ int   g_qnb[BS];                // per-batch queue lengths

// ---------------------------------------------------------------------------
// Kernel 1 (FUSED prep + perm + win): one block per batch, 1024 threads.
// b==0: c = d/2 (reference zeroes the cumsum row) -> hybrid bitonic sort.
// b>0 : assoc-scan-tree fp32 cumsum (reference association); sorted order is
//       a rotation (cv[1..1023] ascending, cv[0] = total + d/2 is the max).
// Then: thread t owns sorted slot t -> copies its h row into g_hp; then the
// window phase (4 rows/thread) computes smax + group unions + wide queue.
// ---------------------------------------------------------------------------
__global__ void __launch_bounds__(1024) prep_kernel(
    const float* __restrict__ d, const float* __restrict__ h,
    const float* __restrict__ sigma)
{
    __shared__ float r[2047];
    __shared__ float sarr[2047];
    __shared__ float c_s[T];
    __shared__ int   i_s[T];
    const int b = blockIdx.x;
    const int t = threadIdx.x;
    const float v = d[b * T + t];

    if (t == 0) g_qnb[b] = 0;      // own-batch queue reset (block-local)

    float key; int idx;
    if (b == 0) {
        // bitonic sort of (d/2, t): smem steps for j>=32, shfl below
        key = 0.5f * v;            // exact; == fadd(0.5*v, 0)
        idx = t;
        float* sv = r;             // reuse scan buffers
        int*   si = (int*)sarr;
        for (int k = 2; k <= T; k <<= 1) {
            for (int j = k >> 1; j >= 32; j >>= 1) {
                sv[t] = key; si[t] = idx;
                __syncthreads();
                int p = t ^ j;
                float pv = sv[p]; int pi = si[p];
                bool keepmin = (((t & k) == 0) == ((t & j) == 0));
                bool take = keepmin ? (pv < key) : (pv > key);
                if (take) { key = pv; idx = pi; }
                __syncthreads();
            }
            const int j0 = (k >> 1) < 16 ? (k >> 1) : 16;
            for (int j = j0; j >= 1; j >>= 1) {
                float pv = __shfl_xor_sync(FULLM, key, j);
                int   pi = __shfl_xor_sync(FULLM, idx, j);
                bool keepmin = (((t & k) == 0) == ((t & j) == 0));
                bool take = keepmin ? (pv < key) : (pv > key);
                if (take) { key = pv; idx = pi; }
            }
        }
        c_s[t] = key;
        i_s[t] = idx;
        __syncthreads();
    } else {
        // fp32 tree scan replicating jax.lax.associative_scan
        r[t] = v;
        __syncthreads();
        {   // upsweep
            int off = 0, n = T;
            while (n > 1) {
                int noff = off + n;
                if (t < (n >> 1))
                    r[noff + t] = __fadd_rn(r[off + 2 * t], r[off + 2 * t + 1]);
                __syncthreads();
                off = noff; n >>= 1;
            }
        }
        if (t == 0) sarr[2046] = r[2046];
        __syncthreads();
        #pragma unroll
        for (int L = 9; L >= 0; --L) {   // downsweep
            const int n    = T >> L;
            const int off  = 2048 - (2048 >> L);
            const int offn = 2048 - (2048 >> (L + 1));
            if (t < n) {
                float val;
                if (t == 0)     val = r[off];
                else if (t & 1) val = sarr[offn + (t >> 1)];
                else            val = __fadd_rn(sarr[offn + (t >> 1) - 1], r[off + t]);
                sarr[off + t] = val;
            }
            __syncthreads();
        }
        float cs = (t == 0) ? sarr[T - 1] : sarr[t - 1];   // roll
        float cv = __fadd_rn(0.5f * v, cs);
        int dest = (t == 0) ? (T - 1) : (t - 1);           // sorted = rotation
        c_s[dest] = cv;
        i_s[dest] = t;
        __syncthreads();
        key = c_s[t];
        idx = i_s[t];
    }

    // emit sorted centers (+pad) and permuted h rows (+pad)
    g_cs[b * PT + t] = key;
    if (t < TPAD) g_cs[b * PT + T + t] = INFINITY;
    {
        const float4* src = (const float4*)h + ((size_t)b * T + idx) * DF4;
        float4* dst = (float4*)g_hp + ((size_t)b * PT + t) * DF4;
        #pragma unroll
        for (int j = 0; j < DF4; ++j) dst[j] = src[j];
        if (t < TPAD) {
            float4* pd = (float4*)g_hp + ((size_t)b * PT + T + t) * DF4;
            #pragma unroll
            for (int j = 0; j < DF4; ++j) pd[j] = make_float4(0.f, 0.f, 0.f, 0.f);
        }
    }

    // ---- window phase: 4 rows per thread (s = ch*1024 + t)
    const float sg     = sigma[0];
    const float two_s2 = 2.0f * sg * sg;

    auto lower = [&](float x) -> int {
        int lo = 0, hi = T;
        while (lo < hi) {
            int m = (lo + hi) >> 1;
            if (c_s[m] > x) hi = m; else lo = m + 1;
        }
        return lo;
    };

    #pragma unroll
    for (int ch = 0; ch < 4; ++ch) {
        const int s = ch * 1024 + t;
        const float tval = (float)s + 1.5f;

        int kc = lower(tval);
        int kA = kc < (T - 1) ? kc : (T - 1);
        int kB = (kc - 1) > 0 ? (kc - 1) : 0;
        float dA  = __fsub_rn(tval, c_s[kA]);
        float dB  = __fsub_rn(tval, c_s[kB]);
        float sqA = __fmul_rn(dA, dA);
        float sqB = __fmul_rn(dB, dB);
        float sqmin = fminf(sqA, sqB);
        g_smax[(size_t)b * SIZE + s] = -__fdiv_rn(sqmin, two_s2);

        const float rr = sqrtf(sqmin + 24.0f * two_s2);
        int klo = lower(tval - rr);
        int khi = lower(tval + rr) - 1;

        #pragma unroll
        for (int o = 1; o < 8; o <<= 1) {     // union over 8 consecutive rows
            klo = min(klo, __shfl_xor_sync(FULLM, klo, o));
            khi = max(khi, __shfl_xor_sync(FULLM, khi, o));
        }
        if ((t & 7) == 0) {
            const int grp = s >> 3;
            g_win[b * GRPS + grp] = make_int2(klo, khi);
            if (khi - klo + 1 > THRESH) {
                int p = atomicAdd(&g_qnb[b], 1);
                g_qb[b][p] = grp;
            }
        }
    }
}

// ---------------------------------------------------------------------------
// Shared inner body (validated R13): chunk-of-4 quad loop.
//   dt=fsub; sq=fmul; sc=-fdiv(sq,2s^2) [POW2: fmul by exact recip == fdiv];
//   e=fsub(sc,smax); w=expf(e). Guard kk>ahi gives exact segment partition.
// ---------------------------------------------------------------------------
template<bool POW2, bool USM>
__device__ __forceinline__ float body(
    const float* __restrict__ cb,            // g_cs + b*PT (global)
    const float* __restrict__ csm,           // staged c (smem), base kbase
    const float4* __restrict__ hpb,          // global h_perm batch base
    const float4* __restrict__ hsm, int kbase,
    int alo, int ahi, int f, float tval, float smax,
    float two_s2, float inv2s2, float4* acc)
{
    float l = 0.0f;
    for (int k0 = alo; k0 <= ahi; k0 += 4) {
        const int kk = k0 + f;
        float cc = USM ? csm[kk - kbase] : __ldg(cb + kk);
        float dt = __fsub_rn(tval, cc);
        float sq = __fmul_rn(dt, dt);
        float sc = POW2 ? -__fmul_rn(sq, inv2s2) : -__fdiv_rn(sq, two_s2);
        float e  = __fsub_rn(sc, smax);
        float w0 = __expf(e);
        if (kk > ahi) w0 = 0.0f;
        float w1 = __shfl_xor_sync(FULLM, w0, 1);
        float w2 = __shfl_xor_sync(FULLM, w0, 2);
        float w3 = __shfl_xor_sync(FULLM, w1, 2);
        l += ((w0 + w1) + (w2 + w3));

        const int r0 = k0 + f, r1 = k0 + (f ^ 1), r2 = k0 + (f ^ 2), r3 = k0 + (f ^ 3);
        #pragma unroll
        for (int j = 0; j < 5; ++j) {
            const int col = f + 4 * j;
            float4 v0 = USM ? hsm[(r0 - kbase) * DF4 + col] : hpb[(size_t)r0 * DF4 + col];
            acc[j].x += w0 * v0.x; acc[j].y += w0 * v0.y;
            acc[j].z += w0 * v0.z; acc[j].w += w0 * v0.w;
            float4 v1 = USM ? hsm[(r1 - kbase) * DF4 + col] : hpb[(size_t)r1 * DF4 + col];
            acc[j].x += w1 * v1.x; acc[j].y += w1 * v1.y;
            acc[j].z += w1 * v1.z; acc[j].w += w1 * v1.w;
            float4 v2 = USM ? hsm[(r2 - kbase) * DF4 + col] : hpb[(size_t)r2 * DF4 + col];
            acc[j].x += w2 * v2.x; acc[j].y += w2 * v2.y;
            acc[j].z += w2 * v2.z; acc[j].w += w2 * v2.w;
            float4 v3 = USM ? hsm[(r3 - kbase) * DF4 + col] : hpb[(size_t)r3 * DF4 + col];
            acc[j].x += w3 * v3.x; acc[j].y += w3 * v3.y;
            acc[j].z += w3 * v3.z; acc[j].w += w3 * v3.w;
        }
    }
    return l;
}

// ---------------------------------------------------------------------------
// Kernel 2a: NARROW groups (unchanged from R15 — measured 23.1us).
// ---------------------------------------------------------------------------
__global__ void __launch_bounds__(TPB) narrow_kernel(
    const float* __restrict__ sigma, float* __restrict__ out)
{
    __shared__ float4 h_sm[KMAX * DF4];      // 48000 B
    __shared__ float  c_sm[KMAX + 4];
    __shared__ int s_klo, s_khi;
    const int b   = blockIdx.y;
    const int bx  = blockIdx.x;
    const int tid = threadIdx.x;
    const int f   = tid & 3;
    const int row = tid >> 2;                // 0..31
    const int s   = bx * RPB + row;
    const int wrp = tid >> 5;                // 0..3

    const int2 wv = g_win[b * GRPS + bx * GPB + wrp];
    const int wlo = wv.x, whi = wv.y, len = whi - wlo + 1;
    const bool active = (len <= THRESH);
    const int alo = wlo, ahi = whi;

    if (tid == 0) { s_klo = 0x7FFFFFFF; s_khi = -1; }
    __syncthreads();
    if (active && (tid & 31) == 0) { atomicMin(&s_klo, alo); atomicMax(&s_khi, ahi); }
    __syncthreads();
    if (s_khi < 0) return;                   // all 4 groups wide (rare)

    const int kbase  = s_klo;
    const int kcount = s_khi + 4 - kbase;    // loop reads rows up to ahi+3
    const bool usm   = (kcount <= KMAX);
    const float* cb  = g_cs + b * PT;
    const float4* __restrict__ hpb = (const float4*)g_hp + (size_t)b * PT * DF4;

    if (usm) {
        const float4* src = hpb + (size_t)kbase * DF4;
        for (int i = tid; i < kcount * DF4; i += TPB) h_sm[i] = src[i];
        for (int i = tid; i < kcount; i += TPB) c_sm[i] = cb[kbase + i];
    }
    __syncthreads();
    if (!active) return;                     // after all block-wide syncs

    const float sg     = sigma[0];
    const float two_s2 = 2.0f * sg * sg;
    const unsigned tb  = __float_as_uint(two_s2);
    const bool pow2    = ((tb & 0x007FFFFFu) == 0u) && (two_s2 > 0.0f);
    const float inv2s2 = 1.0f / two_s2;      // exact reciprocal when pow2
    const float tval   = (float)s + 1.5f;
    const float smax   = g_smax[(size_t)b * SIZE + s];

    float4 acc[5];
    #pragma unroll
    for (int j = 0; j < 5; ++j) acc[j] = make_float4(0.f, 0.f, 0.f, 0.f);

    float l;
    if (pow2) {
        if (usm) l = body<true , true >(cb, c_sm, hpb, h_sm, kbase, alo, ahi, f, tval, smax, two_s2, inv2s2, acc);
        else     l = body<true , false>(cb, c_sm, hpb, h_sm, kbase, alo, ahi, f, tval, smax, two_s2, inv2s2, acc);
    } else {
        if (usm) l = body<false, true >(cb, c_sm, hpb, h_sm, kbase, alo, ahi, f, tval, smax, two_s2, inv2s2, acc);
        else     l = body<false, false>(cb, c_sm, hpb, h_sm, kbase, alo, ahi, f, tval, smax, two_s2, inv2s2, acc);
    }

    const float linv = 1.0f / l;
    float4* o = (float4*)out + ((size_t)b * SIZE + s) * DF4 + f;
    #pragma unroll
    for (int j = 0; j < 5; ++j) {
        float4 v;
        v.x = acc[j].x * linv; v.y = acc[j].y * linv;
        v.z = acc[j].z * linv; v.w = acc[j].w * linv;
        o[4 * j] = v;
    }
}

// ---------------------------------------------------------------------------
// Kernel 2b: WIDE groups from the per-batch queues. One warp per (group,z).
// ---------------------------------------------------------------------------
__global__ void __launch_bounds__(TPB) wide_kernel(
    const float* __restrict__ sigma)
{
    const int tid  = threadIdx.x;
    const int wrp  = tid >> 5;
    const int lane = tid & 31;
    const int f    = lane & 3;
    const int quad = lane >> 2;              // row in group
    const int slot = blockIdx.x * 4 + wrp;
    const int nslots = WGRID * 4;

    const float sg     = sigma[0];
    const float two_s2 = 2.0f * sg * sg;
    const unsigned tb  = __float_as_uint(two_s2);
    const bool pow2    = ((tb & 0x007FFFFFu) == 0u) && (two_s2 > 0.0f);
    const float inv2s2 = 1.0f / two_s2;

    for (int b = 0; b < BS; ++b) {
        const int nb = g_qnb[b] * NZ;
        const float* cb = g_cs + b * PT;
        const float4* __restrict__ hpb =
            (const float4*)g_hp + (size_t)b * PT * DF4;

        for (int item = slot; item < nb; item += nslots) {
            const int grp = g_qb[b][item / NZ];
            const int z   = item % NZ;
            const int s   = grp * 8 + quad;

            const int2 wv = g_win[b * GRPS + grp];
            const int wlo = wv.x, len = wv.y - wv.x + 1;
            const int alo = wlo + (len * z) / NZ;
            const int ahi = wlo + (len * (z + 1)) / NZ - 1;

            const float tval = (float)s + 1.5f;
            const float smax = g_smax[(size_t)b * SIZE + s];

            float4 acc[5];
            #pragma unroll
            for (int j = 0; j < 5; ++j) acc[j] = make_float4(0.f, 0.f, 0.f, 0.f);

            float l;
            if (pow2) l = body<true , false>(cb, (const float*)0, hpb, (const float4*)0, 0,
                                             alo, ahi, f, tval, smax, two_s2, inv2s2, acc);
            else      l = body<false, false>(cb, (const float*)0, hpb, (const float4*)0, 0,
                                             alo, ahi, f, tval, smax, two_s2, inv2s2, acc);

            const size_t rowid = (size_t)b * SIZE + s;
            float4* po = (float4*)g_part + ((size_t)z * NROW + rowid) * DF4 + f;
            #pragma unroll
            for (int j = 0; j < 5; ++j) po[4 * j] = acc[j];
            if (f == 0) g_lpart[(size_t)z * NROW + rowid] = l;
        }
    }
}

// ---------------------------------------------------------------------------
// Kernel 3: combine — queue-driven, touches only WIDE rows.
// One thread per (wide row, float4 column) item.
// ---------------------------------------------------------------------------
__global__ void __launch_bounds__(256) combine_kernel(float* __restrict__ out) {
    const int slot = blockIdx.x * 256 + threadIdx.x;
    const int nslots = CGRID * 256;

    for (int b = 0; b < BS; ++b) {
        const int items = g_qnb[b] * 8 * DF4;   // rows * columns
        for (int i = slot; i < items; i += nslots) {
            const int grp = g_qb[b][i / (8 * DF4)];
            const int rem = i % (8 * DF4);
            const int rw  = rem / DF4;          // row in group
            const int col = rem % DF4;
            const size_t rowid = (size_t)b * SIZE + grp * 8 + rw;
            const size_t e = rowid * DF4 + col;

            float lsum = 0.0f;
            #pragma unroll
            for (int z = 0; z < NZ; ++z)
                lsum += g_lpart[(size_t)z * NROW + rowid];

            float4 v = make_float4(0.f, 0.f, 0.f, 0.f);
            #pragma unroll
            for (int z = 0; z < NZ; ++z) {
                float4 p = ((const float4*)g_part)[(size_t)z * NROW * DF4 + e];
                v.x += p.x; v.y += p.y; v.z += p.z; v.w += p.w;
            }
            const float linv = 1.0f / lsum;
            v.x *= linv; v.y *= linv; v.z *= linv; v.w *= linv;
            ((float4*)out)[e] = v;
        }
    }
}

// ---------------------------------------------------------------------------
extern "C" void kernel_launch(void* const* d_in, const int* in_sizes, int n_in,
                              void* d_out, int out_size) {
    const float* h     = (const float*)d_in[0];  // [16,1024,80]
    const float* d     = (const float*)d_in[1];  // [16,1024]
    const float* sigma = (const float*)d_in[2];  // [1]

    prep_kernel<<<BS, T>>>(d, h, sigma);         // scan/sort + perm + windows
    dim3 ngrid(SIZE / RPB, BS);                  // 128 x 16
    narrow_kernel<<<ngrid, TPB>>>(sigma, (float*)d_out);
    wide_kernel<<<WGRID, TPB>>>(sigma);
    combine_kernel<<<CGRID, 256>>>((float*)d_out);
}

// round 17
// speedup vs baseline: 1.2685x; 1.2685x over previous
#include <cuda_runtime.h>
#include <math.h>

// Problem constants (fixed by setup_inputs)
#define BS    16
#define T     1024
#define DF    80
#define DF4   20
#define SIZE  4096
#define TPB   128        // narrow kernel: quad per row -> 32 rows per block
#define RPB   32
#define GPB   4          // 8-row groups per narrow block
#define NZ    16         // split factor for WIDE groups
#define THRESH 96
#define GRPS  (SIZE / 8) // 512
#define TPAD  8
#define PT    (T + TPAD)
#define NROW  (BS * SIZE)
#define KMAX  150        // narrow h-tile rows in smem (150*320B = 48000B)
#define WGRID 256        // wide kernel blocks (x4 warps = 1024 work slots)
#define CGRID 256        // combine kernel blocks
#define FULLM 0xFFFFFFFFu

// Device scratch (allocation-free)
__device__ float g_cs[BS * PT];            // sorted centers (+INF pad)
__device__ int   g_ci[BS * PT];            // permutation (0 pad)
__device__ __align__(16) float g_hp[BS * PT * DF];   // permuted h (0 pad)
__device__ int2  g_win[BS * GRPS];         // per 8-row group: union {wlo,whi}
__device__ float g_smax[NROW];             // per row: exact max score
__device__ __align__(16) float g_part[(size_t)NZ * NROW * DF];
__device__ float g_lpart[NZ * NROW];
__device__ int   g_qb[BS][GRPS];           // per-batch queues of WIDE groups
__device__ int   g_qnb[BS];                // per-batch queue lengths

// ---------------------------------------------------------------------------
// Kernel 1 (prep + win fused; NO h copy — that stays wide-parallel):
// one block per batch, 1024 threads.
// b==0: c = d/2 (reference zeroes the cumsum row) -> hybrid bitonic sort.
// b>0 : assoc-scan-tree fp32 cumsum (reference association); sorted order is
//       a rotation (cv[1..1023] ascending, cv[0] = total + d/2 is the max).
// Then the window phase (4 rows/thread on smem c_s): per-row smax, per-group
// unions, wide queue.
// ---------------------------------------------------------------------------
__global__ void __launch_bounds__(1024) prep_kernel(
    const float* __restrict__ d, const float* __restrict__ sigma)
{
    __shared__ float r[2047];
    __shared__ float sarr[2047];
    __shared__ float c_s[T];
    __shared__ int   i_s[T];
    const int b = blockIdx.x;
    const int t = threadIdx.x;
    const float v = d[b * T + t];

    if (t == 0) g_qnb[b] = 0;      // own-batch queue reset (block-local)

    if (b == 0) {
        // bitonic sort of (d/2, t): smem steps for j>=32, shfl below
        float key = 0.5f * v;      // exact; == fadd(0.5*v, 0)
        int   idx = t;
        float* sv = r;             // reuse scan buffers
        int*   si = (int*)sarr;
        for (int k = 2; k <= T; k <<= 1) {
            for (int j = k >> 1; j >= 32; j >>= 1) {
                sv[t] = key; si[t] = idx;
                __syncthreads();
                int p = t ^ j;
                float pv = sv[p]; int pi = si[p];
                bool keepmin = (((t & k) == 0) == ((t & j) == 0));
                bool take = keepmin ? (pv < key) : (pv > key);
                if (take) { key = pv; idx = pi; }
                __syncthreads();
            }
            const int j0 = (k >> 1) < 16 ? (k >> 1) : 16;
            for (int j = j0; j >= 1; j >>= 1) {
                float pv = __shfl_xor_sync(FULLM, key, j);
                int   pi = __shfl_xor_sync(FULLM, idx, j);
                bool keepmin = (((t & k) == 0) == ((t & j) == 0));
                bool take = keepmin ? (pv < key) : (pv > key);
                if (take) { key = pv; idx = pi; }
            }
        }
        c_s[t] = key;
        i_s[t] = idx;
        __syncthreads();
    } else {
        // fp32 tree scan replicating jax.lax.associative_scan
        r[t] = v;
        __syncthreads();
        {   // upsweep
            int off = 0, n = T;
            while (n > 1) {
                int noff = off + n;
                if (t < (n >> 1))
                    r[noff + t] = __fadd_rn(r[off + 2 * t], r[off + 2 * t + 1]);
                __syncthreads();
                off = noff; n >>= 1;
            }
        }
        if (t == 0) sarr[2046] = r[2046];
        __syncthreads();
        #pragma unroll
        for (int L = 9; L >= 0; --L) {   // downsweep
            const int n    = T >> L;
            const int off  = 2048 - (2048 >> L);
            const int offn = 2048 - (2048 >> (L + 1));
            if (t < n) {
                float val;
                if (t == 0)     val = r[off];
                else if (t & 1) val = sarr[offn + (t >> 1)];
                else            val = __fadd_rn(sarr[offn + (t >> 1) - 1], r[off + t]);
                sarr[off + t] = val;
            }
            __syncthreads();
        }
        float cs = (t == 0) ? sarr[T - 1] : sarr[t - 1];   // roll
        float cv = __fadd_rn(0.5f * v, cs);
        int dest = (t == 0) ? (T - 1) : (t - 1);           // sorted = rotation
        c_s[dest] = cv;
        i_s[dest] = t;
        __syncthreads();
    }

    // emit sorted centers + permutation (+pad)
    g_cs[b * PT + t] = c_s[t];
    g_ci[b * PT + t] = i_s[t];
    if (t < TPAD) {
        g_cs[b * PT + T + t] = INFINITY;
        g_ci[b * PT + T + t] = 0;
    }

    // ---- window phase: 4 rows per thread (s = ch*1024 + t), c_s in smem
    const float sg     = sigma[0];
    const float two_s2 = 2.0f * sg * sg;

    auto lower = [&](float x) -> int {
        int lo = 0, hi = T;
        while (lo < hi) {
            int m = (lo + hi) >> 1;
            if (c_s[m] > x) hi = m; else lo = m + 1;
        }
        return lo;
    };

    #pragma unroll
    for (int ch = 0; ch < 4; ++ch) {
        const int s = ch * 1024 + t;
        const float tval = (float)s + 1.5f;

        int kc = lower(tval);
        int kA = kc < (T - 1) ? kc : (T - 1);
        int kB = (kc - 1) > 0 ? (kc - 1) : 0;
        float dA  = __fsub_rn(tval, c_s[kA]);
        float dB  = __fsub_rn(tval, c_s[kB]);
        float sqA = __fmul_rn(dA, dA);
        float sqB = __fmul_rn(dB, dB);
        float sqmin = fminf(sqA, sqB);
        g_smax[(size_t)b * SIZE + s] = -__fdiv_rn(sqmin, two_s2);

        const float rr = sqrtf(sqmin + 24.0f * two_s2);
        int klo = lower(tval - rr);
        int khi = lower(tval + rr) - 1;

        #pragma unroll
        for (int o = 1; o < 8; o <<= 1) {     // union over 8 consecutive rows
            klo = min(klo, __shfl_xor_sync(FULLM, klo, o));
            khi = max(khi, __shfl_xor_sync(FULLM, khi, o));
        }
        if ((t & 7) == 0) {
            const int grp = s >> 3;
            g_win[b * GRPS + grp] = make_int2(klo, khi);
            if (khi - klo + 1 > THRESH) {
                int p = atomicAdd(&g_qnb[b], 1);
                g_qb[b][p] = grp;
            }
        }
    }
}

// ---------------------------------------------------------------------------
// Kernel 1b: h_perm[b][k][:] = h[b][ci[b][k]][:]; pad rows zeroed.
// WIDE-parallel (5160 blocks) — full-chip L2 bandwidth for the gather.
// ---------------------------------------------------------------------------
__global__ void perm_kernel(const float* __restrict__ h) {
    const int e = blockIdx.x * blockDim.x + threadIdx.x;
    const int c = e % DF;
    const int k = (e / DF) % PT;
    const int b = e / (DF * PT);
    if (b >= BS) return;
    float v = 0.0f;
    if (k < T) {
        int src = g_ci[b * PT + k];
        v = h[((size_t)b * T + src) * DF + c];
    }
    g_hp[((size_t)b * PT + k) * DF + c] = v;
}

// ---------------------------------------------------------------------------
// Shared inner body (validated R13): chunk-of-4 quad loop.
//   dt=fsub; sq=fmul; sc=-fdiv(sq,2s^2) [POW2: fmul by exact recip == fdiv];
//   e=fsub(sc,smax); w=expf(e). Guard kk>ahi gives exact segment partition.
// ---------------------------------------------------------------------------
template<bool POW2, bool USM>
__device__ __forceinline__ float body(
    const float* __restrict__ cb,            // g_cs + b*PT (global)
    const float* __restrict__ csm,           // staged c (smem), base kbase
    const float4* __restrict__ hpb,          // global h_perm batch base
    const float4* __restrict__ hsm, int kbase,
    int alo, int ahi, int f, float tval, float smax,
    float two_s2, float inv2s2, float4* acc)
{
    float l = 0.0f;
    for (int k0 = alo; k0 <= ahi; k0 += 4) {
        const int kk = k0 + f;
        float cc = USM ? csm[kk - kbase] : __ldg(cb + kk);
        float dt = __fsub_rn(tval, cc);
        float sq = __fmul_rn(dt, dt);
        float sc = POW2 ? -__fmul_rn(sq, inv2s2) : -__fdiv_rn(sq, two_s2);
        float e  = __fsub_rn(sc, smax);
        float w0 = __expf(e);
        if (kk > ahi) w0 = 0.0f;
        float w1 = __shfl_xor_sync(FULLM, w0, 1);
        float w2 = __shfl_xor_sync(FULLM, w0, 2);
        float w3 = __shfl_xor_sync(FULLM, w1, 2);
        l += ((w0 + w1) + (w2 + w3));

        const int r0 = k0 + f, r1 = k0 + (f ^ 1), r2 = k0 + (f ^ 2), r3 = k0 + (f ^ 3);
        #pragma unroll
        for (int j = 0; j < 5; ++j) {
            const int col = f + 4 * j;
            float4 v0 = USM ? hsm[(r0 - kbase) * DF4 + col] : hpb[(size_t)r0 * DF4 + col];
            acc[j].x += w0 * v0.x; acc[j].y += w0 * v0.y;
            acc[j].z += w0 * v0.z; acc[j].w += w0 * v0.w;
            float4 v1 = USM ? hsm[(r1 - kbase) * DF4 + col] : hpb[(size_t)r1 * DF4 + col];
            acc[j].x += w1 * v1.x; acc[j].y += w1 * v1.y;
            acc[j].z += w1 * v1.z; acc[j].w += w1 * v1.w;
            float4 v2 = USM ? hsm[(r2 - kbase) * DF4 + col] : hpb[(size_t)r2 * DF4 + col];
            acc[j].x += w2 * v2.x; acc[j].y += w2 * v2.y;
            acc[j].z += w2 * v2.z; acc[j].w += w2 * v2.w;
            float4 v3 = USM ? hsm[(r3 - kbase) * DF4 + col] : hpb[(size_t)r3 * DF4 + col];
            acc[j].x += w3 * v3.x; acc[j].y += w3 * v3.y;
            acc[j].z += w3 * v3.z; acc[j].w += w3 * v3.w;
        }
    }
    return l;
}

// ---------------------------------------------------------------------------
// Kernel 2a: NARROW groups (unchanged from R15 — measured 23.1us).
// ---------------------------------------------------------------------------
__global__ void __launch_bounds__(TPB) narrow_kernel(
    const float* __restrict__ sigma, float* __restrict__ out)
{
    __shared__ float4 h_sm[KMAX * DF4];      // 48000 B
    __shared__ float  c_sm[KMAX + 4];
    __shared__ int s_klo, s_khi;
    const int b   = blockIdx.y;
    const int bx  = blockIdx.x;
    const int tid = threadIdx.x;
    const int f   = tid & 3;
    const int row = tid >> 2;                // 0..31
    const int s   = bx * RPB + row;
    const int wrp = tid >> 5;                // 0..3

    const int2 wv = g_win[b * GRPS + bx * GPB + wrp];
    const int wlo = wv.x, whi = wv.y, len = whi - wlo + 1;
    const bool active = (len <= THRESH);
    const int alo = wlo, ahi = whi;

    if (tid == 0) { s_klo = 0x7FFFFFFF; s_khi = -1; }
    __syncthreads();
    if (active && (tid & 31) == 0) { atomicMin(&s_klo, alo); atomicMax(&s_khi, ahi); }
    __syncthreads();
    if (s_khi < 0) return;                   // all 4 groups wide (rare)

    const int kbase  = s_klo;
    const int kcount = s_khi + 4 - kbase;    // loop reads rows up to ahi+3
    const bool usm   = (kcount <= KMAX);
    const float* cb  = g_cs + b * PT;
    const float4* __restrict__ hpb = (const float4*)g_hp + (size_t)b * PT * DF4;

    if (usm) {
        const float4* src = hpb + (size_t)kbase * DF4;
        for (int i = tid; i < kcount * DF4; i += TPB) h_sm[i] = src[i];
        for (int i = tid; i < kcount; i += TPB) c_sm[i] = cb[kbase + i];
    }
    __syncthreads();
    if (!active) return;                     // after all block-wide syncs

    const float sg     = sigma[0];
    const float two_s2 = 2.0f * sg * sg;
    const unsigned tb  = __float_as_uint(two_s2);
    const bool pow2    = ((tb & 0x007FFFFFu) == 0u) && (two_s2 > 0.0f);
    const float inv2s2 = 1.0f / two_s2;      // exact reciprocal when pow2
    const float tval   = (float)s + 1.5f;
    const float smax   = g_smax[(size_t)b * SIZE + s];

    float4 acc[5];
    #pragma unroll
    for (int j = 0; j < 5; ++j) acc[j] = make_float4(0.f, 0.f, 0.f, 0.f);

    float l;
    if (pow2) {
        if (usm) l = body<true , true >(cb, c_sm, hpb, h_sm, kbase, alo, ahi, f, tval, smax, two_s2, inv2s2, acc);
        else     l = body<true , false>(cb, c_sm, hpb, h_sm, kbase, alo, ahi, f, tval, smax, two_s2, inv2s2, acc);
    } else {
        if (usm) l = body<false, true >(cb, c_sm, hpb, h_sm, kbase, alo, ahi, f, tval, smax, two_s2, inv2s2, acc);
        else     l = body<false, false>(cb, c_sm, hpb, h_sm, kbase, alo, ahi, f, tval, smax, two_s2, inv2s2, acc);
    }

    const float linv = 1.0f / l;
    float4* o = (float4*)out + ((size_t)b * SIZE + s) * DF4 + f;
    #pragma unroll
    for (int j = 0; j < 5; ++j) {
        float4 v;
        v.x = acc[j].x * linv; v.y = acc[j].y * linv;
        v.z = acc[j].z * linv; v.w = acc[j].w * linv;
        o[4 * j] = v;
    }
}

// ---------------------------------------------------------------------------
// Kernel 2b: WIDE groups from the per-batch queues. One warp per (group,z).
// ---------------------------------------------------------------------------
__global__ void __launch_bounds__(TPB) wide_kernel(
    const float* __restrict__ sigma)
{
    const int tid  = threadIdx.x;
    const int wrp  = tid >> 5;
    const int lane = tid & 31;
    const int f    = lane & 3;
    const int quad = lane >> 2;              // row in group
    const int slot = blockIdx.x * 4 + wrp;
    const int nslots = WGRID * 4;

    const float sg     = sigma[0];
    const float two_s2 = 2.0f * sg * sg;
    const unsigned tb  = __float_as_uint(two_s2);
    const bool pow2    = ((tb & 0x007FFFFFu) == 0u) && (two_s2 > 0.0f);
    const float inv2s2 = 1.0f / two_s2;

    for (int b = 0; b < BS; ++b) {
        const int nb = g_qnb[b] * NZ;
        const float* cb = g_cs + b * PT;
        const float4* __restrict__ hpb =
            (const float4*)g_hp + (size_t)b * PT * DF4;

        for (int item = slot; item < nb; item += nslots) {
            const int grp = g_qb[b][item / NZ];
            const int z   = item % NZ;
            const int s   = grp * 8 + quad;

            const int2 wv = g_win[b * GRPS + grp];
            const int wlo = wv.x, len = wv.y - wv.x + 1;
            const int alo = wlo + (len * z) / NZ;
            const int ahi = wlo + (len * (z + 1)) / NZ - 1;

            const float tval = (float)s + 1.5f;
            const float smax = g_smax[(size_t)b * SIZE + s];

            float4 acc[5];
            #pragma unroll
            for (int j = 0; j < 5; ++j) acc[j] = make_float4(0.f, 0.f, 0.f, 0.f);

            float l;
            if (pow2) l = body<true , false>(cb, (const float*)0, hpb, (const float4*)0, 0,
                                             alo, ahi, f, tval, smax, two_s2, inv2s2, acc);
            else      l = body<false, false>(cb, (const float*)0, hpb, (const float4*)0, 0,
                                             alo, ahi, f, tval, smax, two_s2, inv2s2, acc);

            const size_t rowid = (size_t)b * SIZE + s;
            float4* po = (float4*)g_part + ((size_t)z * NROW + rowid) * DF4 + f;
            #pragma unroll
            for (int j = 0; j < 5; ++j) po[4 * j] = acc[j];
            if (f == 0) g_lpart[(size_t)z * NROW + rowid] = l;
        }
    }
}

// ---------------------------------------------------------------------------
// Kernel 3: combine — queue-driven, touches only WIDE rows.
// CGRID x 256 threads: ~1 item per thread (65K slots vs ~50K items).
// ---------------------------------------------------------------------------
__global__ void __launch_bounds__(256) combine_kernel(float* __restrict__ out) {
    const int slot = blockIdx.x * 256 + threadIdx.x;
    const int nslots = CGRID * 256;

    for (int b = 0; b < BS; ++b) {
        const int items = g_qnb[b] * 8 * DF4;   // rows * columns
        for (int i = slot; i < items; i += nslots) {
            const int grp = g_qb[b][i / (8 * DF4)];
            const int rem = i % (8 * DF4);
            const int rw  = rem / DF4;          // row in group
            const int col = rem % DF4;
            const size_t rowid = (size_t)b * SIZE + grp * 8 + rw;
            const size_t e = rowid * DF4 + col;

            float lsum = 0.0f;
            #pragma unroll
            for (int z = 0; z < NZ; ++z)
                lsum += g_lpart[(size_t)z * NROW + rowid];

            float4 v = make_float4(0.f, 0.f, 0.f, 0.f);
            #pragma unroll
            for (int z = 0; z < NZ; ++z) {
                float4 p = ((const float4*)g_part)[(size_t)z * NROW * DF4 + e];
                v.x += p.x; v.y += p.y; v.z += p.z; v.w += p.w;
            }
            const float linv = 1.0f / lsum;
            v.x *= linv; v.y *= linv; v.z *= linv; v.w *= linv;
            ((float4*)out)[e] = v;
        }
    }
}

// ---------------------------------------------------------------------------
extern "C" void kernel_launch(void* const* d_in, const int* in_sizes, int n_in,
                              void* d_out, int out_size) {
    const float* h     = (const float*)d_in[0];  // [16,1024,80]
    const float* d     = (const float*)d_in[1];  // [16,1024]
    const float* sigma = (const float*)d_in[2];  // [1]

    prep_kernel<<<BS, T>>>(d, sigma);            // scan/sort + windows + queue
    const int pelems = BS * PT * DF;
    perm_kernel<<<(pelems + 255) / 256, 256>>>(h);   // wide-parallel gather

    dim3 ngrid(SIZE / RPB, BS);                  // 128 x 16
    narrow_kernel<<<ngrid, TPB>>>(sigma, (float*)d_out);
    wide_kernel<<<WGRID, TPB>>>(sigma);
    combine_kernel<<<CGRID, 256>>>((float*)d_out);
}